// round 15
// baseline (speedup 1.0000x reference)
#include <cuda_runtime.h>
#include <cstdint>

// GaussianVoxelizer: 2M gaussians -> 640K voxels argmax-by-opacity (min-index
// tiebreak), then per-voxel gather + analytic covariance inverse.
//
// output kernel = lane-parallel gather (~4x fewer L1tex wavefronts than
// thread-per-voxel) + round-3 register-array batching (all 32 LDG
// destinations live in a[32] until the post-loop smem copy -> full MLP).
// Round 14: 51.6us output, regs 57, DRAM 74.7%, occupancy 49% REG-BOUND
// (4 blocks/SM; smem allows 6). This round's single delta:
// __launch_bounds__(kBlk, 5) caps regs at 51 -> 5 blocks/SM (62.5% occ).
// Tripwire: if regs drop to ~40 the allocator re-chunked the gather batch
// (rounds 4-13 failure mode) -> revert.
//
// Phases: 0 keys->(idx,opa) smem; 1 lane l gathers field l of the warp's
// 32 voxels into a[32], then copies to smem; 2 per-voxel covinv from smem
// temps; 3 coalesced float4 writeback; 4 g_keys reset (MUST stay last: an
// earlier reset store fences gather scheduling, rounds 4-10 bisect).
//
// Voxel binning matches XLA's lowering of (x - vol_min) / 0.4: divide by
// constant folds to multiply by reciprocal; 1/0.4f == 2.5f exactly.

namespace {
constexpr int kH = 200, kW = 200, kD = 16;
constexpr int kV = kH * kW * kD;   // 640000
constexpr int kRow = 31;
constexpr int kBlk = 256;
}

__device__ unsigned long long g_keys[kV];   // zero-initialized at module load

__device__ __forceinline__ int gv_flat(float x, float y, float z) {
    int vx = __float2int_rn(__fmul_rn(__fadd_rn(x, 40.0f), 2.5f));
    int vy = __float2int_rn(__fmul_rn(__fadd_rn(y, 40.0f), 2.5f));
    int vz = __float2int_rn(__fmul_rn(__fadd_rn(z, 1.0f), 2.5f));
    vx = min(max(vx, 0), kH - 1);
    vy = min(max(vy, 0), kW - 1);
    vz = min(max(vz, 0), kD - 1);
    return vx * (kW * kD) + vy * kD + vz;
}

__device__ __forceinline__ unsigned long long gv_key(float o, unsigned i) {
    return ((unsigned long long)__float_as_uint(o) << 32) |
           (unsigned long long)(0xFFFFFFFFu - i);
}

__global__ void gv_scatter_kernel(const float* __restrict__ means,
                                  const float* __restrict__ opac,
                                  int n) {
    int t = blockIdx.x * blockDim.x + threadIdx.x;
    int n4 = n >> 2;
    if (t < n4) {
        const float4* pm = reinterpret_cast<const float4*>(means) + 3 * t;
        float4 a = pm[0];
        float4 b = pm[1];
        float4 c = pm[2];
        float4 o = reinterpret_cast<const float4*>(opac)[t];
        unsigned i0 = 4 * t;

        int f0 = gv_flat(a.x, a.y, a.z);
        int f1 = gv_flat(a.w, b.x, b.y);
        int f2 = gv_flat(b.z, b.w, c.x);
        int f3 = gv_flat(c.y, c.z, c.w);

        atomicMax(&g_keys[f0], gv_key(o.x, i0 + 0));
        atomicMax(&g_keys[f1], gv_key(o.y, i0 + 1));
        atomicMax(&g_keys[f2], gv_key(o.z, i0 + 2));
        atomicMax(&g_keys[f3], gv_key(o.w, i0 + 3));
    } else if (t == n4 && (n & 3)) {
        for (int i = n4 * 4; i < n; i++) {
            int f = gv_flat(means[3 * i + 0], means[3 * i + 1],
                            means[3 * i + 2]);
            atomicMax(&g_keys[f], gv_key(opac[i], (unsigned)i));
        }
    }
}

__global__ void __launch_bounds__(kBlk, 5)
gv_output_kernel(const float* __restrict__ means,
                 const float* __restrict__ opac,
                 const float* __restrict__ feats,
                 const float* __restrict__ scales,
                 const float* __restrict__ rots,
                 const float* __restrict__ empty_scalar,
                 float* __restrict__ out) {
    __shared__ float srows[kBlk * kRow];
    __shared__ int   idx_s[kBlk];
    __shared__ float opa_s[kBlk];

    int tid = threadIdx.x;
    int base = blockIdx.x * kBlk;
    int g = base + tid;

    // phase 0: keys -> (idx, opacity) in smem
    unsigned long long key = (g < kV) ? g_keys[g] : 0ull;
    idx_s[tid] = (key != 0ull)
        ? (int)(0xFFFFFFFFu - (unsigned)(key & 0xFFFFFFFFull)) : -1;
    opa_s[tid] = __uint_as_float((unsigned)(key >> 32));
    __syncthreads();

    // phase 1: lane-parallel gather with register-array batching.
    {
        int lane = tid & 31;
        int warp = tid >> 5;
        const float* bptr;
        int mul, off, col;
        if (lane < 3)       { bptr = means;  mul = 3;  off = lane;      col = lane; }
        else if (lane < 20) { bptr = feats;  mul = 17; off = lane - 3;  col = lane + 1; }
        else if (lane < 23) { bptr = scales; mul = 3;  off = lane - 20; col = lane + 2; }
        else if (lane < 27) { bptr = rots;   mul = 4;  off = lane - 23; col = lane + 2; }
        else                { bptr = means;  mul = 0;  off = 0;         col = 0; }
        bool active = (lane < 27);

        float a[32];
#pragma unroll
        for (int v = 0; v < 32; v++) {
            int idx = idx_s[(warp << 5) + v];    // smem broadcast
            a[v] = (active && idx >= 0) ? __ldg(bptr + mul * idx + off)
                                        : 0.0f;
        }
#pragma unroll
        for (int v = 0; v < 32; v++) {
            if (active) srows[((warp << 5) + v) * kRow + col] = a[v];
        }
    }
    __syncthreads();

    // phase 2: per-voxel covinv from smem-staged scales/rots.
    if (g <= kV) {
        float* row = srows + tid * kRow;        // stride 31: conflict-free
        int idx = idx_s[tid];
        float sx, sy, sz, qw, qx, qy, qz;

        if (g == kV) {
            // appended "empty" gaussian row
            row[0] = 0.0f; row[1] = 0.0f; row[2] = 2.2f;
            row[3] = 1.0f;
#pragma unroll
            for (int c = 4; c < 21; c++) row[c] = 0.0f;
            row[21] = empty_scalar[0];
            sx = 100.0f; sy = 100.0f; sz = 8.0f;
            qw = 1.0f; qx = 0.0f; qy = 0.0f; qz = 0.0f;
        } else if (idx >= 0) {
            row[3]  = opa_s[tid];
            row[21] = 0.0f;
            sx = row[22]; sy = row[23]; sz = row[24];
            qw = row[25]; qx = row[26]; qy = row[27]; qz = row[28];
        } else {
            // invalid voxel: zeros + identity covinv inputs
#pragma unroll
            for (int c = 0; c < 22; c++) row[c] = 0.0f;
            sx = 1.0f; sy = 1.0f; sz = 1.0f;
            qw = 1.0f; qx = 0.0f; qy = 0.0f; qz = 0.0f;
        }

        float nrm = sqrtf(qw * qw + qx * qx + qy * qy + qz * qz);
        float inv = 1.0f / nrm;
        qw *= inv; qx *= inv; qy *= inv; qz *= inv;

        float r00 = 1.0f - 2.0f * (qy * qy + qz * qz);
        float r01 = 2.0f * (qx * qy - qw * qz);
        float r02 = 2.0f * (qx * qz + qw * qy);
        float r10 = 2.0f * (qx * qy + qw * qz);
        float r11 = 1.0f - 2.0f * (qx * qx + qz * qz);
        float r12 = 2.0f * (qy * qz - qw * qx);
        float r20 = 2.0f * (qx * qz - qw * qy);
        float r21 = 2.0f * (qy * qz + qw * qx);
        float r22 = 1.0f - 2.0f * (qx * qx + qy * qy);

        // cov = R^T S^2 R  =>  cov_inv = R^T S^-2 R (analytic, symmetric)
        float a0 = 1.0f / (sx * sx);
        float a1 = 1.0f / (sy * sy);
        float a2 = 1.0f / (sz * sz);

        float c00 = r00 * r00 * a0 + r10 * r10 * a1 + r20 * r20 * a2;
        float c01 = r00 * r01 * a0 + r10 * r11 * a1 + r20 * r21 * a2;
        float c02 = r00 * r02 * a0 + r10 * r12 * a1 + r20 * r22 * a2;
        float c11 = r01 * r01 * a0 + r11 * r11 * a1 + r21 * r21 * a2;
        float c12 = r01 * r02 * a0 + r11 * r12 * a1 + r21 * r22 * a2;
        float c22 = r02 * r02 * a0 + r12 * r12 * a1 + r22 * r22 * a2;

        row[22] = c00; row[23] = c01; row[24] = c02;
        row[25] = c01; row[26] = c11; row[27] = c12;
        row[28] = c02; row[29] = c12; row[30] = c22;
    }
    __syncthreads();

    // phase 3: coalesced writeback (float4 over the contiguous block span).
    int nrows = min(kBlk, kV + 1 - base);
    if (nrows > 0) {
        if (nrows == kBlk) {
            constexpr int kVec = kBlk * kRow / 4;   // 1984 float4s
            float4* po = reinterpret_cast<float4*>(out + (size_t)base * kRow);
            const float4* ps = reinterpret_cast<const float4*>(srows);
            for (int e = tid; e < kVec; e += kBlk) {
                po[e] = ps[e];
            }
        } else {
            int nelem = nrows * kRow;
            float* po = out + (size_t)base * kRow;
            for (int e = tid; e < nelem; e += kBlk) {
                po[e] = srows[e];
            }
        }
    }

    // phase 4: reset AFTER the hot path: zero-invariant for next replay.
    if (g < kV) g_keys[g] = 0ull;
}

extern "C" void kernel_launch(void* const* d_in, const int* in_sizes, int n_in,
                              void* d_out, int out_size) {
    const float* means        = (const float*)d_in[0];  // [N,3]
    const float* opac         = (const float*)d_in[1];  // [N,1]
    const float* feats        = (const float*)d_in[2];  // [N,17]
    const float* scales       = (const float*)d_in[3];  // [N,3]
    const float* rots         = (const float*)d_in[4];  // [N,4]
    const float* empty_scalar = (const float*)d_in[5];  // [1]
    float* out = (float*)d_out;                         // [1, V+1, 31]

    int n = in_sizes[0] / 3;

    int nthreads = n / 4 + 1;   // +1 thread handles any scalar tail
    gv_scatter_kernel<<<(nthreads + 255) / 256, 256>>>(means, opac, n);
    gv_output_kernel<<<(kV + 1 + kBlk - 1) / kBlk, kBlk>>>(
        means, opac, feats, scales, rots, empty_scalar, out);
}

// round 16
// speedup vs baseline: 1.0582x; 1.0582x over previous
#include <cuda_runtime.h>
#include <cstdint>

// GaussianVoxelizer: 2M gaussians -> 640K voxels argmax-by-opacity (min-index
// tiebreak), then per-voxel gather + analytic covariance inverse.
//
// output kernel (round 16): WARP-AUTONOMOUS phases. Round-14's winning body
// (lane-parallel gather + a[32] register-array batching, 51.6us, DRAM 75%)
// but with all block barriers removed: each warp handles its 32 voxels
// end-to-end (gather -> covinv -> writeback) with only __syncwarp between
// phases, idx broadcast via __shfl_sync instead of smem. Warps no longer
// convoy at __syncthreads, so gather/compute/writeback of different warps
// overlap. No __launch_bounds minimum: round-15 showed forcing regs 57->48
// cuts per-thread MLP and loses more than the occupancy gains (occupancy
// 59% but DRAM% fell) -- per-thread batch width beats occupancy here.
//
// CODEGEN-CRITICAL: all 32 gather LDG destinations live in a[32] until the
// post-loop smem copy (rounds 4-13: any structure letting ptxas chunk the
// batch collapses MLP). g_keys reset stays at the VERY END (rounds 4-10:
// an earlier reset store fences gather scheduling).
//
// Voxel binning matches XLA's lowering of (x - vol_min) / 0.4: divide by
// constant folds to multiply by reciprocal; 1/0.4f == 2.5f exactly.

namespace {
constexpr int kH = 200, kW = 200, kD = 16;
constexpr int kV = kH * kW * kD;   // 640000
constexpr int kRow = 31;
constexpr int kBlk = 256;
}

__device__ unsigned long long g_keys[kV];   // zero-initialized at module load

__device__ __forceinline__ int gv_flat(float x, float y, float z) {
    int vx = __float2int_rn(__fmul_rn(__fadd_rn(x, 40.0f), 2.5f));
    int vy = __float2int_rn(__fmul_rn(__fadd_rn(y, 40.0f), 2.5f));
    int vz = __float2int_rn(__fmul_rn(__fadd_rn(z, 1.0f), 2.5f));
    vx = min(max(vx, 0), kH - 1);
    vy = min(max(vy, 0), kW - 1);
    vz = min(max(vz, 0), kD - 1);
    return vx * (kW * kD) + vy * kD + vz;
}

__device__ __forceinline__ unsigned long long gv_key(float o, unsigned i) {
    return ((unsigned long long)__float_as_uint(o) << 32) |
           (unsigned long long)(0xFFFFFFFFu - i);
}

__global__ void gv_scatter_kernel(const float* __restrict__ means,
                                  const float* __restrict__ opac,
                                  int n) {
    int t = blockIdx.x * blockDim.x + threadIdx.x;
    int n4 = n >> 2;
    if (t < n4) {
        const float4* pm = reinterpret_cast<const float4*>(means) + 3 * t;
        float4 a = pm[0];
        float4 b = pm[1];
        float4 c = pm[2];
        float4 o = reinterpret_cast<const float4*>(opac)[t];
        unsigned i0 = 4 * t;

        int f0 = gv_flat(a.x, a.y, a.z);
        int f1 = gv_flat(a.w, b.x, b.y);
        int f2 = gv_flat(b.z, b.w, c.x);
        int f3 = gv_flat(c.y, c.z, c.w);

        atomicMax(&g_keys[f0], gv_key(o.x, i0 + 0));
        atomicMax(&g_keys[f1], gv_key(o.y, i0 + 1));
        atomicMax(&g_keys[f2], gv_key(o.z, i0 + 2));
        atomicMax(&g_keys[f3], gv_key(o.w, i0 + 3));
    } else if (t == n4 && (n & 3)) {
        for (int i = n4 * 4; i < n; i++) {
            int f = gv_flat(means[3 * i + 0], means[3 * i + 1],
                            means[3 * i + 2]);
            atomicMax(&g_keys[f], gv_key(opac[i], (unsigned)i));
        }
    }
}

__global__ void __launch_bounds__(kBlk)
gv_output_kernel(const float* __restrict__ means,
                 const float* __restrict__ opac,
                 const float* __restrict__ feats,
                 const float* __restrict__ scales,
                 const float* __restrict__ rots,
                 const float* __restrict__ empty_scalar,
                 float* __restrict__ out) {
    __shared__ float srows[kBlk * kRow];

    int tid  = threadIdx.x;
    int lane = tid & 31;
    int warp = tid >> 5;
    int base = blockIdx.x * kBlk;
    int wbeg = base + (warp << 5);      // first voxel of this warp
    int g = wbeg + lane;

    // phase 0 (per-thread): key -> idx, opacity in registers.
    unsigned long long key = (g < kV) ? g_keys[g] : 0ull;
    int my_idx = (key != 0ull)
        ? (int)(0xFFFFFFFFu - (unsigned)(key & 0xFFFFFFFFull)) : -1;
    float my_opa = __uint_as_float((unsigned)(key >> 32));

    // phase 1: lane-parallel gather with register-array batching.
    // Lane l loads field l of each of the warp's 32 voxels into a[32];
    // idx of voxel v comes via shfl from lane v. a[] is copied to smem
    // ONLY AFTER the loop so all 32 LDGs stay in flight.
    // Column map: means->0..2, feats->4..20, scales->22..24 (temp),
    // rots->25..28 (temp). Opacity (col 3) comes from the key.
    {
        const float* bptr;
        int mul, off, col;
        if (lane < 3)       { bptr = means;  mul = 3;  off = lane;      col = lane; }
        else if (lane < 20) { bptr = feats;  mul = 17; off = lane - 3;  col = lane + 1; }
        else if (lane < 23) { bptr = scales; mul = 3;  off = lane - 20; col = lane + 2; }
        else if (lane < 27) { bptr = rots;   mul = 4;  off = lane - 23; col = lane + 2; }
        else                { bptr = means;  mul = 0;  off = 0;         col = 0; }
        bool active = (lane < 27);

        float a[32];
#pragma unroll
        for (int v = 0; v < 32; v++) {
            int idx = __shfl_sync(0xFFFFFFFFu, my_idx, v);
            a[v] = (active && idx >= 0) ? __ldg(bptr + mul * idx + off)
                                        : 0.0f;
        }
#pragma unroll
        for (int v = 0; v < 32; v++) {
            if (active) srows[((warp << 5) + v) * kRow + col] = a[v];
        }
    }
    __syncwarp();

    // phase 2: per-voxel covinv from smem-staged scales/rots (own warp's
    // rows only -> warp-level sync suffices).
    if (g <= kV) {
        float* row = srows + tid * kRow;        // stride 31: conflict-free
        float sx, sy, sz, qw, qx, qy, qz;

        if (g == kV) {
            // appended "empty" gaussian row
            row[0] = 0.0f; row[1] = 0.0f; row[2] = 2.2f;
            row[3] = 1.0f;
#pragma unroll
            for (int c = 4; c < 21; c++) row[c] = 0.0f;
            row[21] = empty_scalar[0];
            sx = 100.0f; sy = 100.0f; sz = 8.0f;
            qw = 1.0f; qx = 0.0f; qy = 0.0f; qz = 0.0f;
        } else if (my_idx >= 0) {
            row[3]  = my_opa;
            row[21] = 0.0f;
            sx = row[22]; sy = row[23]; sz = row[24];
            qw = row[25]; qx = row[26]; qy = row[27]; qz = row[28];
        } else {
            // invalid voxel: zeros + identity covinv inputs
#pragma unroll
            for (int c = 0; c < 22; c++) row[c] = 0.0f;
            sx = 1.0f; sy = 1.0f; sz = 1.0f;
            qw = 1.0f; qx = 0.0f; qy = 0.0f; qz = 0.0f;
        }

        float nrm = sqrtf(qw * qw + qx * qx + qy * qy + qz * qz);
        float inv = 1.0f / nrm;
        qw *= inv; qx *= inv; qy *= inv; qz *= inv;

        float r00 = 1.0f - 2.0f * (qy * qy + qz * qz);
        float r01 = 2.0f * (qx * qy - qw * qz);
        float r02 = 2.0f * (qx * qz + qw * qy);
        float r10 = 2.0f * (qx * qy + qw * qz);
        float r11 = 1.0f - 2.0f * (qx * qx + qz * qz);
        float r12 = 2.0f * (qy * qz - qw * qx);
        float r20 = 2.0f * (qx * qz - qw * qy);
        float r21 = 2.0f * (qy * qz + qw * qx);
        float r22 = 1.0f - 2.0f * (qx * qx + qy * qy);

        // cov = R^T S^2 R  =>  cov_inv = R^T S^-2 R (analytic, symmetric)
        float a0 = 1.0f / (sx * sx);
        float a1 = 1.0f / (sy * sy);
        float a2 = 1.0f / (sz * sz);

        float c00 = r00 * r00 * a0 + r10 * r10 * a1 + r20 * r20 * a2;
        float c01 = r00 * r01 * a0 + r10 * r11 * a1 + r20 * r21 * a2;
        float c02 = r00 * r02 * a0 + r10 * r12 * a1 + r20 * r22 * a2;
        float c11 = r01 * r01 * a0 + r11 * r11 * a1 + r21 * r21 * a2;
        float c12 = r01 * r02 * a0 + r11 * r12 * a1 + r21 * r22 * a2;
        float c22 = r02 * r02 * a0 + r12 * r12 * a1 + r22 * r22 * a2;

        row[22] = c00; row[23] = c01; row[24] = c02;
        row[25] = c01; row[26] = c11; row[27] = c12;
        row[28] = c02; row[29] = c12; row[30] = c22;
    }
    __syncwarp();

    // phase 3: per-warp coalesced writeback of this warp's 32 rows
    // (992 floats = 248 float4s, span and smem base both 16B-aligned).
    {
        int wend = min(wbeg + 32, kV + 1);
        int wrows = wend - wbeg;
        if (wrows == 32) {
            const float4* ps =
                reinterpret_cast<const float4*>(srows + (warp << 5) * kRow);
            float4* po = reinterpret_cast<float4*>(out + (size_t)wbeg * kRow);
#pragma unroll
            for (int e = lane; e < 32 * kRow / 4; e += 32) {
                po[e] = ps[e];
            }
        } else if (wrows > 0) {
            int nelem = wrows * kRow;
            const float* ps = srows + (warp << 5) * kRow;
            float* po = out + (size_t)wbeg * kRow;
            for (int e = lane; e < nelem; e += 32) {
                po[e] = ps[e];
            }
        }
    }

    // phase 4: reset AFTER the hot path: zero-invariant for next replay.
    if (g < kV) g_keys[g] = 0ull;
}

extern "C" void kernel_launch(void* const* d_in, const int* in_sizes, int n_in,
                              void* d_out, int out_size) {
    const float* means        = (const float*)d_in[0];  // [N,3]
    const float* opac         = (const float*)d_in[1];  // [N,1]
    const float* feats        = (const float*)d_in[2];  // [N,17]
    const float* scales       = (const float*)d_in[3];  // [N,3]
    const float* rots         = (const float*)d_in[4];  // [N,4]
    const float* empty_scalar = (const float*)d_in[5];  // [1]
    float* out = (float*)d_out;                         // [1, V+1, 31]

    int n = in_sizes[0] / 3;

    int nthreads = n / 4 + 1;   // +1 thread handles any scalar tail
    gv_scatter_kernel<<<(nthreads + 255) / 256, 256>>>(means, opac, n);
    gv_output_kernel<<<(kV + 1 + kBlk - 1) / kBlk, kBlk>>>(
        means, opac, feats, scales, rots, empty_scalar, out);
}